// round 5
// baseline (speedup 1.0000x reference)
#include <cuda_runtime.h>

#define TT 64
#define FULL 0xffffffffu

__host__ __device__ constexpr int cnotF(int k) {
    int b0 = k & 1, b1 = (k >> 1) & 1, b2 = (k >> 2) & 1, b3 = (k >> 3) & 1;
    b1 ^= b0; b2 ^= b1; b3 ^= b2; b0 ^= b3;
    return b0 | (b1 << 1) | (b2 << 2) | (b3 << 3);
}
__host__ __device__ constexpr int cnotFinv(int s) {
    int r = 0;
    for (int k = 0; k < 16; ++k) if (cnotF(k) == s) r = k;
    return r;
}
__host__ __device__ constexpr int popc4(int k) {
    return (k & 1) + ((k >> 1) & 1) + ((k >> 2) & 1) + ((k >> 3) & 1);
}

__device__ __forceinline__ float sx(float v, int m) { return __shfl_xor_sync(FULL, v, m); }

__global__ void __launch_bounds__(128, 1)
qlstm16p(const float* __restrict__ x,
         const float* __restrict__ w_in,  const float* __restrict__ b_in,
         const float* __restrict__ w_out, const float* __restrict__ b_out,
         const float* __restrict__ wq_f,  const float* __restrict__ wq_i,
         const float* __restrict__ wq_u,  const float* __restrict__ wq_o,
         const float* __restrict__ w_fc,  const float* __restrict__ b_fc,
         float* __restrict__ out, int B)
{
    const int tid = blockIdx.x * 128 + threadIdx.x;
    const int e0  = tid >> 4;
    const int gl  = tid & 15;         // lane in 16-group
    const int g   = gl >> 2;          // gate (f,i,u,o)
    const int sub = gl & 3;           // slot bits (3,2)
    const int b16 = (threadIdx.x & 31) & ~15;
    const int grp = threadIdx.x >> 4; // group index in block (0..7)
    const int e   = (e0 < B) ? e0 : B - 1;

    // ---------------- pre-pass: xproj -> shared (h-independent) ----------------
    __shared__ float4 sxp[8][TT];
    {
        const float* xe = x + (long)e * TT * 32;
        float acc[4][4];
#pragma unroll
        for (int i = 0; i < 4; ++i)
#pragma unroll
            for (int w = 0; w < 4; ++w) acc[i][w] = 0.f;
#pragma unroll
        for (int c = 0; c < 8; ++c) {
            float4 wv[4];
#pragma unroll
            for (int w = 0; w < 4; ++w)
                wv[w] = *reinterpret_cast<const float4*>(&w_in[w * 40 + 8 + 4 * c]);
#pragma unroll
            for (int i = 0; i < 4; ++i) {
                float4 xv = *reinterpret_cast<const float4*>(&xe[(gl * 4 + i) * 32 + 4 * c]);
#pragma unroll
                for (int w = 0; w < 4; ++w) {
                    acc[i][w] = fmaf(xv.x, wv[w].x, acc[i][w]);
                    acc[i][w] = fmaf(xv.y, wv[w].y, acc[i][w]);
                    acc[i][w] = fmaf(xv.z, wv[w].z, acc[i][w]);
                    acc[i][w] = fmaf(xv.w, wv[w].w, acc[i][w]);
                }
            }
        }
#pragma unroll
        for (int i = 0; i < 4; ++i)
            sxp[grp][gl * 4 + i] = make_float4(0.5f * acc[i][0], 0.5f * acc[i][1],
                                               0.5f * acc[i][2], 0.5f * acc[i][3]);
    }
    __syncthreads();

    const float* wq = (g == 0) ? wq_f : (g == 1) ? wq_i : (g == 2) ? wq_u : wq_o;

    // ---- circuit constants ----
    float hw0[4], C[4], Sv[4];
#pragma unroll
    for (int w = 0; w < 4; ++w) {
        hw0[w] = 0.5f * (__ldg(&wq[w]) + __ldg(&b_in[w]));
        float a = 0.5f * __ldg(&wq[4 + w]);
        C[w] = cosf(a); Sv[w] = sinf(a);
    }
    // h-projection weights, permuted to this lane's h-register order:
    // h8 order = comps {2s,2s+1, 2(s^1),2(s^1)+1, 2(s^2),2(s^2)+1, 2(s^3),2(s^3)+1}
    float Wh8[4][8];
#pragma unroll
    for (int w = 0; w < 4; ++w)
#pragma unroll
        for (int k = 0; k < 8; ++k) {
            const int comp = 2 * (sub ^ (k >> 1)) + (k & 1);
            Wh8[w][k] = 0.5f * __ldg(&w_in[w * 40 + comp]);
        }
    // output proj rows for comps {2*sub, 2*sub+1}, Hadamard characters folded in
    const float chiP = (popc4(sub) & 1) ? -1.f : 1.f;
    const float chiB = (sub & 1) ? -1.f : 1.f;
    const float chi[4] = {chiP, 1.f, chiB, chiP};
    float Wo[2][4], bo[2];
#pragma unroll
    for (int i = 0; i < 2; ++i) {
        bo[i] = __ldg(&b_out[2 * sub + i]);
#pragma unroll
        for (int w = 0; w < 4; ++w) Wo[i][w] = __ldg(&w_out[(2 * sub + i) * 4 + w]) * chi[w];
    }

    // ---- per-lane sign tables (slots s = 4*sub + u) ----
    const int FLIPT[4] = {0, 12, 11, 7};   // Finv(4*sub)
    const int flip = FLIPT[sub];
    float sg3[4], t0[4], b1s[4], b2s[4];
#pragma unroll
    for (int u = 0; u < 4; ++u) {
        const int cls  = popc4(cnotFinv(u) ^ flip) & 3;
        const int c3p  = popc4(cnotFinv(u) ^ flip ^ 11) & 3;
        const int c0p  = popc4(cnotFinv(u ^ 1) ^ flip) & 3;
        const int c1p  = popc4(cnotFinv(u ^ 2) ^ flip) & 3;
        const int c2p  = popc4(cnotFinv(u) ^ flip ^ 12) & 3;
        sg3[u] = (((c3p + 1 - cls) & 3) == 0) ?  Sv[3] : -Sv[3];
        t0 [u] = (((c0p - cls) & 3) == 0)     ? -Sv[0] :  Sv[0];
        b1s[u] = (((c1p - cls) & 3) == 0)     ?  Sv[1] : -Sv[1];
        b2s[u] = (((c2p - cls) & 3) == 0)     ?  Sv[2] : -Sv[2];
    }
    const bool f0 = flip & 1, f1 = flip & 2, f2 = flip & 4, f3 = flip & 8;

    const float sc  = (g == 2) ? -2.f : -1.f;
    const float isT = (g == 2) ?  1.f :  0.f;

    float cc[2] = {0.f, 0.f};
    float h8[8] = {0.f, 0.f, 0.f, 0.f, 0.f, 0.f, 0.f, 0.f};

#pragma unroll 1
    for (int t = 0; t < TT; ++t) {
        // ---- angles: local h-dot + precomputed x-part (broadcast LDS) ----
        float4 xq = sxp[grp][t];
        const float xarr[4] = {xq.x, xq.y, xq.z, xq.w};
        float pw[4];
#pragma unroll
        for (int w = 0; w < 4; ++w) {
            float a = xarr[w] + hw0[w];
#pragma unroll
            for (int k = 0; k < 8; ++k) a = fmaf(h8[k], Wh8[w][k], a);
            pw[w] = a;
        }

        float cw[4], sw[4];
#pragma unroll
        for (int w = 0; w < 4; ++w) __sincosf(pw[w], &sw[w], &cw[w]);

        const float ec0 = f0 ? sw[0] : cw[0], es0 = f0 ? cw[0] : sw[0];
        const float ec1 = f1 ? sw[1] : cw[1], es1 = f1 ? cw[1] : sw[1];
        const float ec2 = f2 ? sw[2] : cw[2], es2 = f2 ? cw[2] : sw[2];
        const float ec3 = f3 ? sw[3] : cw[3];

        // ---- product build (Finv(0..3)={0,3,6,5}, bit3=0) ----
        const float mc = ec2 * ec3, ms = es2 * ec3;
        float r0 = (ec0 * ec1) * mc;
        float r1 = (es0 * es1) * mc;
        float r2 = (ec0 * es1) * ms;
        float r3 = (es0 * ec1) * ms;

        // ---- RX wire3 (mask 8): cross-lane sx(,2), pure-real Givens ----
        {
            float p0 = sx(r0, 2), p1 = sx(r1, 2), p2 = sx(r2, 2), p3 = sx(r3, 2);
            r0 = fmaf(C[3], r0, sg3[0] * p0);
            r1 = fmaf(C[3], r1, sg3[1] * p1);
            r2 = fmaf(C[3], r2, sg3[2] * p2);
            r3 = fmaf(C[3], r3, sg3[3] * p3);
        }
        // ---- RX wire0 (mask 1): local, pure -> complex ----
        float Re[4], Im[4];
        Re[0] = C[0] * r0;  Im[0] = t0[0] * r1;
        Re[1] = C[0] * r1;  Im[1] = t0[1] * r0;
        Re[2] = C[0] * r2;  Im[2] = t0[2] * r3;
        Re[3] = C[0] * r3;  Im[3] = t0[3] * r2;

        // ---- RX wire1 (mask 2): local complex, pairs (0,2),(1,3) ----
#pragma unroll
        for (int u = 0; u < 2; ++u) {
            const int v = u | 2;
            float ar = Re[u], ai = Im[u], br = Re[v], bi = Im[v];
            Re[u] = fmaf(b1s[u], bi, C[1] * ar); Im[u] = fmaf(-b1s[u], br, C[1] * ai);
            Re[v] = fmaf(b1s[v], ai, C[1] * br); Im[v] = fmaf(-b1s[v], ar, C[1] * bi);
        }
        // ---- RX wire2 (mask 4): cross-lane sx(,1), complex ----
#pragma unroll
        for (int u = 0; u < 4; ++u) {
            float rp = sx(Re[u], 1), ip = sx(Im[u], 1);
            Re[u] = fmaf(b2s[u], ip, C[2] * Re[u]);
            Im[u] = fmaf(-b2s[u], rp, C[2] * Im[u]);
        }

        // ---- probabilities + Walsh partials ----
        float q0 = fmaf(Re[0], Re[0], Im[0] * Im[0]);
        float q1 = fmaf(Re[1], Re[1], Im[1] * Im[1]);
        float q2 = fmaf(Re[2], Re[2], Im[2] * Im[2]);
        float q3 = fmaf(Re[3], Re[3], Im[3] * Im[3]);
        float d0 = q0 - q2, d1 = q1 - q3;
        float P0 = d0 + d1, P1 = d0 - d1;

        float a0 = P0 - sx(P0, 1);
        float tB = sx(P1, 1);
        float bp = P1 + tB, bm = P1 - tB;
        float ex0 = a0 - sx(a0, 2);
        float ex1 = bp + sx(bp, 2);
        float u2  = sx(bm, 2);
        float ex2 = bm + u2;
        float ex3 = bm - u2;

        // ---- activations for own 2 comps ----
        float act0, act1;
        {
            float gv0 = bo[0], gv1 = bo[1];
            gv0 = fmaf(ex0, Wo[0][0], gv0); gv1 = fmaf(ex0, Wo[1][0], gv1);
            gv0 = fmaf(ex1, Wo[0][1], gv0); gv1 = fmaf(ex1, Wo[1][1], gv1);
            gv0 = fmaf(ex2, Wo[0][2], gv0); gv1 = fmaf(ex2, Wo[1][2], gv1);
            gv0 = fmaf(ex3, Wo[0][3], gv0); gv1 = fmaf(ex3, Wo[1][3], gv1);
            float tE0 = __expf(sc * gv0), tE1 = __expf(sc * gv1);
            act0 = __fdividef(fmaf(-isT, tE0, 1.f), 1.f + tE0);
            act1 = __fdividef(fmaf(-isT, tE1, 1.f), 1.f + tE1);
        }

        // ---- gather f,i,u,o; cell update; full-h broadcast ----
        {
            const int s0 = b16 + sub;
            float fv0 = __shfl_sync(FULL, act0, s0);
            float fv1 = __shfl_sync(FULL, act1, s0);
            float iv0 = __shfl_sync(FULL, act0, s0 + 4);
            float iv1 = __shfl_sync(FULL, act1, s0 + 4);
            float uv0 = __shfl_sync(FULL, act0, s0 + 8);
            float uv1 = __shfl_sync(FULL, act1, s0 + 8);
            float ov0 = __shfl_sync(FULL, act0, s0 + 12);
            float ov1 = __shfl_sync(FULL, act1, s0 + 12);

            float c0n = fmaf(fv0, cc[0], iv0 * uv0);
            float c1n = fmaf(fv1, cc[1], iv1 * uv1);
            cc[0] = c0n; cc[1] = c1n;
            c0n = fminf(fmaxf(c0n, -15.f), 15.f);
            c1n = fminf(fmaxf(c1n, -15.f), 15.f);
            float e0v = __expf(-2.f * c0n);
            float e1v = __expf(-2.f * c1n);
            float h0n = ov0 * __fdividef(1.f - e0v, 1.f + e0v);
            float h1n = ov1 * __fdividef(1.f - e1v, 1.f + e1v);

            float o0 = sx(h0n, 1), o1 = sx(h1n, 1);
            float p0 = sx(h0n, 2), p1 = sx(h1n, 2);
            float p2 = sx(o0, 2),  p3 = sx(o1, 2);
            h8[0] = h0n; h8[1] = h1n; h8[2] = o0; h8[3] = o1;
            h8[4] = p0;  h8[5] = p1;  h8[6] = p2; h8[7] = p3;
        }
    }

    // ---- final projection (h comps {2sub,2sub+1} live in h8[0],h8[1]) ----
    float p = h8[0] * __ldg(&w_fc[2 * sub]);
    p = fmaf(h8[1], __ldg(&w_fc[2 * sub + 1]), p);
    p += sx(p, 1);
    p += sx(p, 2);
    if (gl == 0 && e0 < B) out[e0] = p + __ldg(&b_fc[0]);
}

extern "C" void kernel_launch(void* const* d_in, const int* in_sizes, int n_in,
                              void* d_out, int out_size) {
    const float* x     = (const float*)d_in[0];
    const float* w_in  = (const float*)d_in[1];
    const float* b_in  = (const float*)d_in[2];
    const float* w_out = (const float*)d_in[3];
    const float* b_out = (const float*)d_in[4];
    const float* wq_f  = (const float*)d_in[5];
    const float* wq_i  = (const float*)d_in[6];
    const float* wq_u  = (const float*)d_in[7];
    const float* wq_o  = (const float*)d_in[8];
    const float* w_fc  = (const float*)d_in[9];
    const float* b_fc  = (const float*)d_in[10];

    int B = in_sizes[0] / (TT * 32);
    int threads = B * 16;
    int blocks = (threads + 127) / 128;
    qlstm16p<<<blocks, 128>>>(x, w_in, b_in, w_out, b_out,
                              wq_f, wq_i, wq_u, wq_o, w_fc, b_fc,
                              (float*)d_out, B);
}

// round 6
// speedup vs baseline: 1.2326x; 1.2326x over previous
#include <cuda_runtime.h>

#define TT 64
#define FULL 0xffffffffu

__host__ __device__ constexpr int cnotF(int k) {
    int b0 = k & 1, b1 = (k >> 1) & 1, b2 = (k >> 2) & 1, b3 = (k >> 3) & 1;
    b1 ^= b0; b2 ^= b1; b3 ^= b2; b0 ^= b3;
    return b0 | (b1 << 1) | (b2 << 2) | (b3 << 3);
}
__host__ __device__ constexpr int cnotFinv(int s) {
    int r = 0;
    for (int k = 0; k < 16; ++k) if (cnotF(k) == s) r = k;
    return r;
}
__host__ __device__ constexpr int popc4(int k) {
    return (k & 1) + ((k >> 1) & 1) + ((k >> 2) & 1) + ((k >> 3) & 1);
}

__device__ __forceinline__ float sx(float v, int m) { return __shfl_xor_sync(FULL, v, m); }
__device__ __forceinline__ float tanhap(float v) {
    float r;
    asm("tanh.approx.f32 %0, %1;" : "=f"(r) : "f"(v));
    return r;
}

__global__ void __launch_bounds__(128, 1)
qlstm16t(const float* __restrict__ x,
         const float* __restrict__ w_in,  const float* __restrict__ b_in,
         const float* __restrict__ w_out, const float* __restrict__ b_out,
         const float* __restrict__ wq_f,  const float* __restrict__ wq_i,
         const float* __restrict__ wq_u,  const float* __restrict__ wq_o,
         const float* __restrict__ w_fc,  const float* __restrict__ b_fc,
         float* __restrict__ out, int B)
{
    const int tid = blockIdx.x * 128 + threadIdx.x;
    const int e0  = tid >> 4;
    const int gl  = tid & 15;         // lane in 16-group
    const int g   = gl >> 2;          // gate (f,i,u,o)
    const int sub = gl & 3;           // slot bits (3,2)
    const int b16 = (threadIdx.x & 31) & ~15;
    const int grp = threadIdx.x >> 4; // group in block (0..7)
    const int e   = (e0 < B) ? e0 : B - 1;

    // ---------------- pre-pass: xproj -> shared (h-independent) ----------------
    __shared__ float4 sxp[8][TT];
    {
        const float* xe = x + (long)e * TT * 32;
        float acc[4][4];
#pragma unroll
        for (int i = 0; i < 4; ++i)
#pragma unroll
            for (int w = 0; w < 4; ++w) acc[i][w] = 0.f;
#pragma unroll
        for (int c = 0; c < 8; ++c) {
            float4 wv[4];
#pragma unroll
            for (int w = 0; w < 4; ++w)
                wv[w] = *reinterpret_cast<const float4*>(&w_in[w * 40 + 8 + 4 * c]);
#pragma unroll
            for (int i = 0; i < 4; ++i) {
                float4 xv = *reinterpret_cast<const float4*>(&xe[(gl * 4 + i) * 32 + 4 * c]);
#pragma unroll
                for (int w = 0; w < 4; ++w) {
                    acc[i][w] = fmaf(xv.x, wv[w].x, acc[i][w]);
                    acc[i][w] = fmaf(xv.y, wv[w].y, acc[i][w]);
                    acc[i][w] = fmaf(xv.z, wv[w].z, acc[i][w]);
                    acc[i][w] = fmaf(xv.w, wv[w].w, acc[i][w]);
                }
            }
        }
#pragma unroll
        for (int i = 0; i < 4; ++i)
            sxp[grp][gl * 4 + i] = make_float4(0.5f * acc[i][0], 0.5f * acc[i][1],
                                               0.5f * acc[i][2], 0.5f * acc[i][3]);
    }
    __syncthreads();

    const float* wq = (g == 0) ? wq_f : (g == 1) ? wq_i : (g == 2) ? wq_u : wq_o;

    // ---- circuit constants ----
    float hw0[4], C[4], Sv[4];
#pragma unroll
    for (int w = 0; w < 4; ++w) {
        hw0[w] = 0.5f * (__ldg(&wq[w]) + __ldg(&b_in[w]));
        float a = 0.5f * __ldg(&wq[4 + w]);
        C[w] = cosf(a); Sv[w] = sinf(a);
    }
    // h-projection weights for own 2 comps (pre-scaled 0.5)
    float Wh2[4][2];
#pragma unroll
    for (int w = 0; w < 4; ++w)
#pragma unroll
        for (int j = 0; j < 2; ++j)
            Wh2[w][j] = 0.5f * __ldg(&w_in[w * 40 + 2 * sub + j]);

    // output proj rows, Hadamard chars + activation prescale folded in
    const float chiP = (popc4(sub) & 1) ? -1.f : 1.f;
    const float chiB = (sub & 1) ? -1.f : 1.f;
    const float chi[4] = {chiP, 1.f, chiB, chiP};
    const float asc = (g == 2) ? 1.f : 0.5f;    // tanh gate: z ; sigmoid: z/2
    const float A1  = (g == 2) ? 1.f : 0.5f;    // act = A1*tanh + A2
    const float A2  = (g == 2) ? 0.f : 0.5f;
    float Wo[2][4], bo[2];
#pragma unroll
    for (int i = 0; i < 2; ++i) {
        bo[i] = asc * __ldg(&b_out[2 * sub + i]);
#pragma unroll
        for (int w = 0; w < 4; ++w)
            Wo[i][w] = asc * chi[w] * __ldg(&w_out[(2 * sub + i) * 4 + w]);
    }

    // ---- per-lane sign tables (slots s = 4*sub + u) ----
    const int FLIPT[4] = {0, 12, 11, 7};   // Finv(4*sub)
    const int flip = FLIPT[sub];
    float sg3[4], t0[4], b1s[4], b2s[4];
#pragma unroll
    for (int u = 0; u < 4; ++u) {
        const int cls  = popc4(cnotFinv(u) ^ flip) & 3;
        const int c3p  = popc4(cnotFinv(u) ^ flip ^ 11) & 3;
        const int c0p  = popc4(cnotFinv(u ^ 1) ^ flip) & 3;
        const int c1p  = popc4(cnotFinv(u ^ 2) ^ flip) & 3;
        const int c2p  = popc4(cnotFinv(u) ^ flip ^ 12) & 3;
        sg3[u] = (((c3p + 1 - cls) & 3) == 0) ?  Sv[3] : -Sv[3];
        t0 [u] = (((c0p - cls) & 3) == 0)     ? -Sv[0] :  Sv[0];
        b1s[u] = (((c1p - cls) & 3) == 0)     ?  Sv[1] : -Sv[1];
        b2s[u] = (((c2p - cls) & 3) == 0)     ?  Sv[2] : -Sv[2];
    }
    const bool f0 = flip & 1, f1 = flip & 2, f2 = flip & 4, f3 = flip & 8;

    float cc0 = 0.f, cc1 = 0.f;       // own c comps {2sub, 2sub+1}
    float h0  = 0.f, h1  = 0.f;       // own h comps {2sub, 2sub+1}

#pragma unroll 1
    for (int t = 0; t < TT; ++t) {
        // ---- h-projection: 2-FMA partials + 2-stage sub-lane butterfly ----
        float4 xq = sxp[grp][t];
        float xk[4] = {xq.x + hw0[0], xq.y + hw0[1], xq.z + hw0[2], xq.w + hw0[3]};
        float pw[4];
#pragma unroll
        for (int w = 0; w < 4; ++w)
            pw[w] = fmaf(h0, Wh2[w][0], h1 * Wh2[w][1]);
#pragma unroll
        for (int w = 0; w < 4; ++w) pw[w] += sx(pw[w], 1);
#pragma unroll
        for (int w = 0; w < 4; ++w) pw[w] += sx(pw[w], 2);

        float cw[4], sw[4];
#pragma unroll
        for (int w = 0; w < 4; ++w) __sincosf(pw[w] + xk[w], &sw[w], &cw[w]);

        const float ec0 = f0 ? sw[0] : cw[0], es0 = f0 ? cw[0] : sw[0];
        const float ec1 = f1 ? sw[1] : cw[1], es1 = f1 ? cw[1] : sw[1];
        const float ec2 = f2 ? sw[2] : cw[2], es2 = f2 ? cw[2] : sw[2];
        const float ec3 = f3 ? sw[3] : cw[3];

        // ---- product build (Finv(0..3)={0,3,6,5}, bit3=0) ----
        const float mc = ec2 * ec3, ms = es2 * ec3;
        float r0 = (ec0 * ec1) * mc;
        float r1 = (es0 * es1) * mc;
        float r2 = (ec0 * es1) * ms;
        float r3 = (es0 * ec1) * ms;

        // ---- RX wire3 (mask 8): cross-lane sx(,2), pure-real Givens ----
        {
            float p0 = sx(r0, 2), p1 = sx(r1, 2), p2 = sx(r2, 2), p3 = sx(r3, 2);
            r0 = fmaf(C[3], r0, sg3[0] * p0);
            r1 = fmaf(C[3], r1, sg3[1] * p1);
            r2 = fmaf(C[3], r2, sg3[2] * p2);
            r3 = fmaf(C[3], r3, sg3[3] * p3);
        }
        // ---- RX wire0 (mask 1): local, pure -> complex ----
        float Re[4], Im[4];
        Re[0] = C[0] * r0;  Im[0] = t0[0] * r1;
        Re[1] = C[0] * r1;  Im[1] = t0[1] * r0;
        Re[2] = C[0] * r2;  Im[2] = t0[2] * r3;
        Re[3] = C[0] * r3;  Im[3] = t0[3] * r2;

        // ---- RX wire1 (mask 2): local complex, pairs (0,2),(1,3) ----
#pragma unroll
        for (int u = 0; u < 2; ++u) {
            const int v = u | 2;
            float ar = Re[u], ai = Im[u], br = Re[v], bi = Im[v];
            Re[u] = fmaf(b1s[u], bi, C[1] * ar); Im[u] = fmaf(-b1s[u], br, C[1] * ai);
            Re[v] = fmaf(b1s[v], ai, C[1] * br); Im[v] = fmaf(-b1s[v], ar, C[1] * bi);
        }
        // ---- RX wire2 (mask 4): cross-lane sx(,1), complex ----
#pragma unroll
        for (int u = 0; u < 4; ++u) {
            float rp = sx(Re[u], 1), ip = sx(Im[u], 1);
            Re[u] = fmaf(b2s[u], ip, C[2] * Re[u]);
            Im[u] = fmaf(-b2s[u], rp, C[2] * Im[u]);
        }

        // ---- probabilities + Walsh partials (parallel shfl form) ----
        float q0 = fmaf(Re[0], Re[0], Im[0] * Im[0]);
        float q1 = fmaf(Re[1], Re[1], Im[1] * Im[1]);
        float q2 = fmaf(Re[2], Re[2], Im[2] * Im[2]);
        float q3 = fmaf(Re[3], Re[3], Im[3] * Im[3]);
        float d0 = q0 - q2, d1 = q1 - q3;
        float P0 = d0 + d1, P1 = d0 - d1;

        float Aq = sx(P0, 1), Bq = sx(P0, 2), Cq = sx(P0, 3);
        float Dq = sx(P1, 1), Eq = sx(P1, 2), Fq = sx(P1, 3);
        float ex0 = (P0 - Aq) - (Bq - Cq);
        float ex1 = (P1 + Dq) + (Eq + Fq);
        float em  = P1 - Dq, ep = Eq - Fq;
        float ex2 = em + ep;
        float ex3 = em - ep;

        // ---- activations for own 2 comps (tanh.approx) ----
        float gv0 = bo[0], gv1 = bo[1];
        gv0 = fmaf(ex0, Wo[0][0], gv0); gv1 = fmaf(ex0, Wo[1][0], gv1);
        gv0 = fmaf(ex1, Wo[0][1], gv0); gv1 = fmaf(ex1, Wo[1][1], gv1);
        gv0 = fmaf(ex2, Wo[0][2], gv0); gv1 = fmaf(ex2, Wo[1][2], gv1);
        gv0 = fmaf(ex3, Wo[0][3], gv0); gv1 = fmaf(ex3, Wo[1][3], gv1);
        float act0 = fmaf(A1, tanhap(gv0), A2);
        float act1 = fmaf(A1, tanhap(gv1), A2);

        // ---- gather f,i,u,o; cell update (tanh.approx, no clamp) ----
        {
            const int s0 = b16 + sub;
            float fv0 = __shfl_sync(FULL, act0, s0);
            float fv1 = __shfl_sync(FULL, act1, s0);
            float iv0 = __shfl_sync(FULL, act0, s0 + 4);
            float iv1 = __shfl_sync(FULL, act1, s0 + 4);
            float uv0 = __shfl_sync(FULL, act0, s0 + 8);
            float uv1 = __shfl_sync(FULL, act1, s0 + 8);
            float ov0 = __shfl_sync(FULL, act0, s0 + 12);
            float ov1 = __shfl_sync(FULL, act1, s0 + 12);

            cc0 = fmaf(fv0, cc0, iv0 * uv0);
            cc1 = fmaf(fv1, cc1, iv1 * uv1);
            h0 = ov0 * tanhap(cc0);
            h1 = ov1 * tanhap(cc1);
        }
    }

    // ---- final projection (own comps; reduce over sub lanes) ----
    float p = h0 * __ldg(&w_fc[2 * sub]);
    p = fmaf(h1, __ldg(&w_fc[2 * sub + 1]), p);
    p += sx(p, 1);
    p += sx(p, 2);
    if (gl == 0 && e0 < B) out[e0] = p + __ldg(&b_fc[0]);
}

extern "C" void kernel_launch(void* const* d_in, const int* in_sizes, int n_in,
                              void* d_out, int out_size) {
    const float* x     = (const float*)d_in[0];
    const float* w_in  = (const float*)d_in[1];
    const float* b_in  = (const float*)d_in[2];
    const float* w_out = (const float*)d_in[3];
    const float* b_out = (const float*)d_in[4];
    const float* wq_f  = (const float*)d_in[5];
    const float* wq_i  = (const float*)d_in[6];
    const float* wq_u  = (const float*)d_in[7];
    const float* wq_o  = (const float*)d_in[8];
    const float* w_fc  = (const float*)d_in[9];
    const float* b_fc  = (const float*)d_in[10];

    int B = in_sizes[0] / (TT * 32);
    int threads = B * 16;
    int blocks = (threads + 127) / 128;
    qlstm16t<<<blocks, 128>>>(x, w_in, b_in, w_out, b_out,
                              wq_f, wq_i, wq_u, wq_o, w_fc, b_fc,
                              (float*)d_out, B);
}